// round 1
// baseline (speedup 1.0000x reference)
#include <cuda_runtime.h>
#include <cstdint>

// Problem constants
#define NNODES   50000
#define NEDGES   800000
#define DIM      64
#define NG       64
#define KIN      192           // 2*DIM + NG
#define TE       128           // edges (or nodes) per block tile
#define PITCH    132           // TE + 4 padding (float units)
#define RCUT     3.0f

// ---------------------------------------------------------------------------
// Scratch: per-node message accumulator (12.8 MB). __device__ global (no alloc).
// ---------------------------------------------------------------------------
__device__ float g_msg[NNODES * DIM];

__device__ __forceinline__ float fsilu(float v)    { return v / (1.0f + __expf(-v)); }
__device__ __forceinline__ float fsigmoid(float v) { return 1.0f / (1.0f + __expf(-v)); }

__device__ __forceinline__ void red_add_v4(float* addr, float a, float b, float c, float d) {
    asm volatile("red.global.add.v4.f32 [%0], {%1, %2, %3, %4};"
                 :: "l"(addr), "f"(a), "f"(b), "f"(c), "f"(d) : "memory");
}

// ---------------------------------------------------------------------------
// Register-tiled shared-memory GEMM fragment:
//   acc[4][8] += A[k][e0..e0+3] * W[k][j0..j0+7],  A pitch = PITCH, W pitch = 64
// ---------------------------------------------------------------------------
__device__ __forceinline__ void gemm_tile(const float* __restrict__ Abuf,
                                          const float* __restrict__ Wbuf,
                                          int K, int e0, int j0, float acc[4][8]) {
#pragma unroll
    for (int ee = 0; ee < 4; ++ee)
#pragma unroll
        for (int jj = 0; jj < 8; ++jj) acc[ee][jj] = 0.0f;

#pragma unroll 2
    for (int k = 0; k < K; ++k) {
        const float4 a  = *(const float4*)(Abuf + k * PITCH + e0);
        const float4 b0 = *(const float4*)(Wbuf + (k << 6) + j0);
        const float4 b1 = *(const float4*)(Wbuf + (k << 6) + j0 + 4);
        const float av[4] = {a.x, a.y, a.z, a.w};
        const float bv[8] = {b0.x, b0.y, b0.z, b0.w, b1.x, b1.y, b1.z, b1.w};
#pragma unroll
        for (int ee = 0; ee < 4; ++ee)
#pragma unroll
            for (int jj = 0; jj < 8; ++jj)
                acc[ee][jj] = fmaf(av[ee], bv[jj], acc[ee][jj]);
    }
}

// Write silu(acc + bias) transposed into Tbuf[j][e] (pitch PITCH), float4 over e.
__device__ __forceinline__ void store_silu_T(float* __restrict__ Tbuf, int e0, int j0,
                                             const float acc[4][8],
                                             const float* __restrict__ bias) {
#pragma unroll
    for (int jj = 0; jj < 8; ++jj) {
        const float b = bias[j0 + jj];
        float4 v;
        v.x = fsilu(acc[0][jj] + b);
        v.y = fsilu(acc[1][jj] + b);
        v.z = fsilu(acc[2][jj] + b);
        v.w = fsilu(acc[3][jj] + b);
        *(float4*)(Tbuf + (j0 + jj) * PITCH + e0) = v;
    }
}

// ---------------------------------------------------------------------------
// Init: zero g_msg, copy x into the x-section of out.
// ---------------------------------------------------------------------------
__global__ void init_kernel(const float* __restrict__ x, float* __restrict__ out) {
    const int tid    = blockIdx.x * blockDim.x + threadIdx.x;
    const int stride = gridDim.x * blockDim.x;
    for (int i = tid; i < NNODES * DIM; i += stride) g_msg[i] = 0.0f;
    float* xo = out + (size_t)NNODES * DIM;
    for (int i = tid; i < NNODES * 3; i += stride) xo[i] = x[i];
}

// ---------------------------------------------------------------------------
// Edge kernel: 128 edges / block, 256 threads.
//  inp = [h_dst | h_src | rbf]  -> silu(GEMM Wm1) -> silu(GEMM Wm2) -> m
//  att = sigmoid(m.Wa + ba); m *= att*mask; scatter m -> g_msg
//  u = silu(m.Wx1 + bx1); dm = tanh(u.Wx2); scatter dirs*dm*mask -> x_out
// ---------------------------------------------------------------------------
__global__ __launch_bounds__(256, 1)
void edge_kernel(const float* __restrict__ h,   const float* __restrict__ x,
                 const int*   __restrict__ edst, const int*  __restrict__ esrc,
                 const float* __restrict__ means, const float* __restrict__ stds,
                 const float* __restrict__ Wm1, const float* __restrict__ bm1,
                 const float* __restrict__ Wm2, const float* __restrict__ bm2,
                 const float* __restrict__ Wa,  const float* __restrict__ ba,
                 const float* __restrict__ Wx1, const float* __restrict__ bx1,
                 const float* __restrict__ Wx2,
                 float* __restrict__ out) {
    extern __shared__ float sm[];
    float* A     = sm;                    // [KIN][PITCH]; later aliased: t1 rows 0..63,
                                          // m rows 64..127, u rows 128..191
    float* W1s   = A + KIN * PITCH;       // 192*64
    float* W2s   = W1s + KIN * 64;        // 64*64
    float* Wx1s  = W2s + 64 * 64;         // 64*64
    float* bm1s  = Wx1s + 64 * 64;        // 64
    float* bm2s  = bm1s + 64;
    float* bx1s  = bm2s + 64;
    float* Was   = bx1s + 64;
    float* Wx2s  = Was + 64;
    float* scale_s = Wx2s + 64;           // 128
    float* mask_s  = scale_s + TE;        // 128
    float* dirx  = mask_s + TE;           // 128
    float* diry  = dirx + TE;
    float* dirz  = diry + TE;
    float* bas   = dirz + TE;             // 1 (+3 pad)
    int*   dst_s = (int*)(bas + 4);       // 128

    const int tid = threadIdx.x;

    // ---- stage weights ----
    {
        const float4* s1 = (const float4*)Wm1;  float4* d1 = (float4*)W1s;
        for (int i = tid; i < (KIN * 64) / 4; i += 256) d1[i] = s1[i];
        const float4* s2 = (const float4*)Wm2;  float4* d2 = (float4*)W2s;
        for (int i = tid; i < (64 * 64) / 4; i += 256) d2[i] = s2[i];
        const float4* s3 = (const float4*)Wx1;  float4* d3 = (float4*)Wx1s;
        for (int i = tid; i < (64 * 64) / 4; i += 256) d3[i] = s3[i];
        if (tid < 64) {
            bm1s[tid] = bm1[tid];  bm2s[tid] = bm2[tid];
            bx1s[tid] = bx1[tid];  Was[tid]  = Wa[tid];
            Wx2s[tid] = Wx2[tid];
        }
        if (tid == 0) bas[0] = ba[0];
    }

    // ---- build A tile (2 threads per edge) ----
    const int ebase = blockIdx.x * TE;
    {
        const int e    = tid >> 1;
        const int half = tid & 1;
        const int ge   = ebase + e;
        const int nd   = edst[ge];
        const int ns   = esrc[ge];
        const float dx = x[nd * 3 + 0] - x[ns * 3 + 0];
        const float dy = x[nd * 3 + 1] - x[ns * 3 + 1];
        const float dz = x[nd * 3 + 2] - x[ns * 3 + 2];
        const float dist = sqrtf(dx * dx + dy * dy + dz * dz);
        if (half == 0) {
            const float inv = 1.0f / dist;
            dirx[e] = dx * inv;  diry[e] = dy * inv;  dirz[e] = dz * inv;
            mask_s[e] = (dist <= RCUT) ? 1.0f : 0.0f;
            dst_s[e]  = nd;
        }
        const int f0 = half * 32;
        const float4* hd = (const float4*)(h + (size_t)nd * DIM + f0);
        const float4* hs = (const float4*)(h + (size_t)ns * DIM + f0);
#pragma unroll
        for (int i = 0; i < 8; ++i) {
            const float4 v = hd[i];
            const int f = f0 + i * 4;
            A[(f + 0) * PITCH + e] = v.x;  A[(f + 1) * PITCH + e] = v.y;
            A[(f + 2) * PITCH + e] = v.z;  A[(f + 3) * PITCH + e] = v.w;
        }
#pragma unroll
        for (int i = 0; i < 8; ++i) {
            const float4 v = hs[i];
            const int f = 64 + f0 + i * 4;
            A[(f + 0) * PITCH + e] = v.x;  A[(f + 1) * PITCH + e] = v.y;
            A[(f + 2) * PITCH + e] = v.z;  A[(f + 3) * PITCH + e] = v.w;
        }
#pragma unroll 8
        for (int i = 0; i < 32; ++i) {
            const int g = f0 + i;
            const float t = (dist - __ldg(means + g)) / __ldg(stds + g);
            A[(128 + g) * PITCH + e] = __expf(-0.5f * t * t);
        }
    }
    __syncthreads();

    const int e0 = (tid & 31) * 4;   // 4 edges per thread
    const int j0 = (tid >> 5) * 8;   // 8 output features per thread
    float acc[4][8];

    // ---- layer 1: [128,192] @ [192,64] ----
    gemm_tile(A, W1s, KIN, e0, j0, acc);
    __syncthreads();                       // all reads of A done
    float* t1 = A;                         // rows 0..63
    store_silu_T(t1, e0, j0, acc, bm1s);
    __syncthreads();

    // ---- layer 2: [128,64] @ [64,64] ----
    gemm_tile(t1, W2s, 64, e0, j0, acc);
    float* mtile = A + 64 * PITCH;         // rows 64..127 (dead A region)
    store_silu_T(mtile, e0, j0, acc, bm2s);
    __syncthreads();

    // ---- attention + mask ----
    if (tid < TE) {
        const int e = tid;
        float s = bas[0];
#pragma unroll 8
        for (int j = 0; j < 64; ++j) s = fmaf(mtile[j * PITCH + e], Was[j], s);
        scale_s[e] = fsigmoid(s) * mask_s[e];
    }
    __syncthreads();

    // ---- scale m in place ----
    for (int i = 0; i < (64 * TE) / 256; ++i) {
        const int lin = tid + i * 256;
        const int e = lin & (TE - 1);
        const int j = lin >> 7;
        mtile[j * PITCH + e] *= scale_s[e];
    }
    __syncthreads();

    // ---- scatter m -> g_msg (vectorized reductions) ----
    for (int i = 0; i < (TE * 16) / 256; ++i) {
        const int q  = tid + i * 256;
        const int e  = q & (TE - 1);
        const int c4 = (q >> 7) * 4;
        const float v0 = mtile[(c4 + 0) * PITCH + e];
        const float v1 = mtile[(c4 + 1) * PITCH + e];
        const float v2 = mtile[(c4 + 2) * PITCH + e];
        const float v3 = mtile[(c4 + 3) * PITCH + e];
        red_add_v4(&g_msg[dst_s[e] * DIM + c4], v0, v1, v2, v3);
    }

    // ---- x path: u = silu(m @ Wx1 + bx1) ----
    gemm_tile(mtile, Wx1s, 64, e0, j0, acc);
    float* utile = A + 128 * PITCH;        // rows 128..191 (dead A region)
    store_silu_T(utile, e0, j0, acc, bx1s);
    __syncthreads();

    // ---- disp magnitude + scatter into x_out ----
    if (tid < TE) {
        const int e = tid;
        float s = 0.0f;
#pragma unroll 8
        for (int j = 0; j < 64; ++j) s = fmaf(utile[j * PITCH + e], Wx2s[j], s);
        const float w = tanhf(s) * mask_s[e];
        float* xo = out + (size_t)NNODES * DIM + dst_s[e] * 3;
        atomicAdd(xo + 0, dirx[e] * w);
        atomicAdd(xo + 1, diry[e] * w);
        atomicAdd(xo + 2, dirz[e] * w);
    }
}

// ---------------------------------------------------------------------------
// Node kernel: h_out = h + silu([h | msg] @ Wh1 + bh1) @ Wh2 + bh2
// 128 nodes / block, 256 threads.
// ---------------------------------------------------------------------------
__global__ __launch_bounds__(256, 1)
void node_kernel(const float* __restrict__ h,
                 const float* __restrict__ Wh1, const float* __restrict__ bh1,
                 const float* __restrict__ Wh2, const float* __restrict__ bh2,
                 float* __restrict__ out) {
    extern __shared__ float sm[];
    float* A   = sm;                   // [128][PITCH]; t1 aliases rows 0..63 later
    float* W1s = A + 128 * PITCH;      // 128*64
    float* W2s = W1s + 128 * 64;       // 64*64
    float* b1s = W2s + 64 * 64;        // 64
    float* b2s = b1s + 64;             // 64

    const int tid = threadIdx.x;
    {
        const float4* s1 = (const float4*)Wh1;  float4* d1 = (float4*)W1s;
        for (int i = tid; i < (128 * 64) / 4; i += 256) d1[i] = s1[i];
        const float4* s2 = (const float4*)Wh2;  float4* d2 = (float4*)W2s;
        for (int i = tid; i < (64 * 64) / 4; i += 256) d2[i] = s2[i];
        if (tid < 64) { b1s[tid] = bh1[tid]; b2s[tid] = bh2[tid]; }
    }

    const int nbase = blockIdx.x * TE;
    {
        const int nl   = tid >> 1;
        const int half = tid & 1;
        const int n    = nbase + nl;
        const bool ok  = (n < NNODES);
        const float4* src = ok
            ? (half ? (const float4*)(g_msg + (size_t)n * DIM)
                    : (const float4*)(h + (size_t)n * DIM))
            : (const float4*)nullptr;
        const int kbase = half * 64;
#pragma unroll
        for (int i = 0; i < 16; ++i) {
            float4 v = ok ? src[i] : make_float4(0.f, 0.f, 0.f, 0.f);
            const int k = kbase + i * 4;
            A[(k + 0) * PITCH + nl] = v.x;  A[(k + 1) * PITCH + nl] = v.y;
            A[(k + 2) * PITCH + nl] = v.z;  A[(k + 3) * PITCH + nl] = v.w;
        }
    }
    __syncthreads();

    const int e0 = (tid & 31) * 4;
    const int j0 = (tid >> 5) * 8;
    float acc[4][8];

    gemm_tile(A, W1s, 128, e0, j0, acc);
    __syncthreads();
    float* t1 = A;
    store_silu_T(t1, e0, j0, acc, b1s);
    __syncthreads();

    gemm_tile(t1, W2s, 64, e0, j0, acc);

#pragma unroll
    for (int ee = 0; ee < 4; ++ee) {
        const int n = nbase + e0 + ee;
        if (n < NNODES) {
            const float4 h0 = *(const float4*)(h + (size_t)n * DIM + j0);
            const float4 h1 = *(const float4*)(h + (size_t)n * DIM + j0 + 4);
            float4 o0, o1;
            o0.x = acc[ee][0] + b2s[j0 + 0] + h0.x;
            o0.y = acc[ee][1] + b2s[j0 + 1] + h0.y;
            o0.z = acc[ee][2] + b2s[j0 + 2] + h0.z;
            o0.w = acc[ee][3] + b2s[j0 + 3] + h0.w;
            o1.x = acc[ee][4] + b2s[j0 + 4] + h1.x;
            o1.y = acc[ee][5] + b2s[j0 + 5] + h1.y;
            o1.z = acc[ee][6] + b2s[j0 + 6] + h1.z;
            o1.w = acc[ee][7] + b2s[j0 + 7] + h1.w;
            *(float4*)(out + (size_t)n * DIM + j0)     = o0;
            *(float4*)(out + (size_t)n * DIM + j0 + 4) = o1;
        }
    }
}

// ---------------------------------------------------------------------------
// Launch
// ---------------------------------------------------------------------------
static const int EDGE_SMEM =
    (KIN * PITCH + KIN * 64 + 64 * 64 + 64 * 64 + 64 * 5 + TE * 2 + TE * 3 + 4 + TE)
    * (int)sizeof(float);
static const int NODE_SMEM =
    (128 * PITCH + 128 * 64 + 64 * 64 + 128) * (int)sizeof(float);

extern "C" void kernel_launch(void* const* d_in, const int* in_sizes, int n_in,
                              void* d_out, int out_size) {
    const float* h     = (const float*)d_in[0];
    const float* x     = (const float*)d_in[1];
    const int*   edst  = (const int*)  d_in[2];
    const int*   esrc  = (const int*)  d_in[3];
    const float* means = (const float*)d_in[4];
    const float* stds  = (const float*)d_in[5];
    const float* Wm1   = (const float*)d_in[6];
    const float* bm1   = (const float*)d_in[7];
    const float* Wm2   = (const float*)d_in[8];
    const float* bm2   = (const float*)d_in[9];
    const float* Wa    = (const float*)d_in[10];
    const float* ba    = (const float*)d_in[11];
    const float* Wx1   = (const float*)d_in[12];
    const float* bx1   = (const float*)d_in[13];
    const float* Wx2   = (const float*)d_in[14];
    const float* Wh1   = (const float*)d_in[15];
    const float* bh1   = (const float*)d_in[16];
    const float* Wh2   = (const float*)d_in[17];
    const float* bh2   = (const float*)d_in[18];
    float* out = (float*)d_out;

    cudaFuncSetAttribute(edge_kernel, cudaFuncAttributeMaxDynamicSharedMemorySize, EDGE_SMEM);
    cudaFuncSetAttribute(node_kernel, cudaFuncAttributeMaxDynamicSharedMemorySize, NODE_SMEM);

    init_kernel<<<592, 256>>>(x, out);
    edge_kernel<<<NEDGES / TE, 256, EDGE_SMEM>>>(
        h, x, edst, esrc, means, stds,
        Wm1, bm1, Wm2, bm2, Wa, ba, Wx1, bx1, Wx2, out);
    node_kernel<<<(NNODES + TE - 1) / TE, 256, NODE_SMEM>>>(
        h, Wh1, bh1, Wh2, bh2, out);
}

// round 8
// speedup vs baseline: 1.1749x; 1.1749x over previous
#include <cuda_runtime.h>
#include <cstdint>

// Problem constants
#define NNODES   50000
#define NEDGES   800000
#define DIM      64
#define NG       64
#define KIN      192           // 2*DIM + NG
#define TE       128           // edges (or nodes) per block tile
#define PITCH    132           // TE + 4 padding (float units)
#define RCUT     3.0f

// ---------------------------------------------------------------------------
// Scratch: per-node message accumulator (12.8 MB). __device__ global (no alloc).
// ---------------------------------------------------------------------------
__device__ float g_msg[NNODES * DIM];

__device__ __forceinline__ float fsilu(float v)    { return v / (1.0f + __expf(-v)); }
__device__ __forceinline__ float fsigmoid(float v) { return 1.0f / (1.0f + __expf(-v)); }

__device__ __forceinline__ void red_add_v4(float* addr, float a, float b, float c, float d) {
    asm volatile("red.global.add.v4.f32 [%0], {%1, %2, %3, %4};"
                 :: "l"(addr), "f"(a), "f"(b), "f"(c), "f"(d) : "memory");
}

// ---- packed f32x2 helpers (sm_100+: full fp32 rate needs FFMA2) ----
__device__ __forceinline__ unsigned long long pack2(float lo, float hi) {
    unsigned long long r;
    asm("mov.b64 %0, {%1, %2};" : "=l"(r) : "f"(lo), "f"(hi));
    return r;
}
__device__ __forceinline__ void fma2(unsigned long long& d,
                                     unsigned long long a, unsigned long long b) {
    asm("fma.rn.f32x2 %0, %1, %2, %3;" : "=l"(d) : "l"(a), "l"(b), "l"(d));
}
__device__ __forceinline__ void unpack2(unsigned long long v, float& lo, float& hi) {
    asm("mov.b64 {%0, %1}, %2;" : "=f"(lo), "=f"(hi) : "l"(v));
}

// ---------------------------------------------------------------------------
// Register-tiled shared-memory GEMM fragment with packed f32x2 math:
//   acc2[ee][jp] (+= lanes {j0+2jp, j0+2jp+1}) over 4 edges x 8 cols.
//   A pitch = PITCH, W pitch = 64. W pairs load packed directly from smem.
// ---------------------------------------------------------------------------
__device__ __forceinline__ void gemm_tile2(const float* __restrict__ Abuf,
                                           const float* __restrict__ Wbuf,
                                           int K, int e0, int j0,
                                           unsigned long long acc2[4][4]) {
#pragma unroll
    for (int ee = 0; ee < 4; ++ee)
#pragma unroll
        for (int jp = 0; jp < 4; ++jp) acc2[ee][jp] = 0ull;

#pragma unroll 4
    for (int k = 0; k < K; ++k) {
        const float4 a = *(const float4*)(Abuf + k * PITCH + e0);
        const ulonglong2 w0 = *(const ulonglong2*)(Wbuf + (k << 6) + j0);
        const ulonglong2 w1 = *(const ulonglong2*)(Wbuf + (k << 6) + j0 + 4);
        unsigned long long aa[4];
        aa[0] = pack2(a.x, a.x);  aa[1] = pack2(a.y, a.y);
        aa[2] = pack2(a.z, a.z);  aa[3] = pack2(a.w, a.w);
        const unsigned long long wv[4] = {w0.x, w0.y, w1.x, w1.y};
#pragma unroll
        for (int ee = 0; ee < 4; ++ee)
#pragma unroll
            for (int jp = 0; jp < 4; ++jp)
                fma2(acc2[ee][jp], aa[ee], wv[jp]);
    }
}

__device__ __forceinline__ void unpack_acc(const unsigned long long acc2[4][4],
                                           float acc[4][8]) {
#pragma unroll
    for (int ee = 0; ee < 4; ++ee)
#pragma unroll
        for (int jp = 0; jp < 4; ++jp)
            unpack2(acc2[ee][jp], acc[ee][2 * jp], acc[ee][2 * jp + 1]);
}

// Write silu(acc + bias) transposed into Tbuf[j][e] (pitch PITCH), float4 over e.
__device__ __forceinline__ void store_silu_T(float* __restrict__ Tbuf, int e0, int j0,
                                             const float acc[4][8],
                                             const float* __restrict__ bias) {
#pragma unroll
    for (int jj = 0; jj < 8; ++jj) {
        const float b = bias[j0 + jj];
        float4 v;
        v.x = fsilu(acc[0][jj] + b);
        v.y = fsilu(acc[1][jj] + b);
        v.z = fsilu(acc[2][jj] + b);
        v.w = fsilu(acc[3][jj] + b);
        *(float4*)(Tbuf + (j0 + jj) * PITCH + e0) = v;
    }
}

// ---------------------------------------------------------------------------
// Init: zero g_msg, copy x into the x-section of out.
// ---------------------------------------------------------------------------
__global__ void init_kernel(const float* __restrict__ x, float* __restrict__ out) {
    const int tid    = blockIdx.x * blockDim.x + threadIdx.x;
    const int stride = gridDim.x * blockDim.x;
    for (int i = tid; i < NNODES * DIM; i += stride) g_msg[i] = 0.0f;
    float* xo = out + (size_t)NNODES * DIM;
    for (int i = tid; i < NNODES * 3; i += stride) xo[i] = x[i];
}

// ---------------------------------------------------------------------------
// Edge kernel: 128 edges / block, 256 threads.
// ---------------------------------------------------------------------------
__global__ __launch_bounds__(256, 1)
void edge_kernel(const float* __restrict__ h,   const float* __restrict__ x,
                 const int*   __restrict__ edst, const int*  __restrict__ esrc,
                 const float* __restrict__ means, const float* __restrict__ stds,
                 const float* __restrict__ Wm1, const float* __restrict__ bm1,
                 const float* __restrict__ Wm2, const float* __restrict__ bm2,
                 const float* __restrict__ Wa,  const float* __restrict__ ba,
                 const float* __restrict__ Wx1, const float* __restrict__ bx1,
                 const float* __restrict__ Wx2,
                 float* __restrict__ out) {
    extern __shared__ float sm[];
    float* A     = sm;                    // [KIN][PITCH]; aliased later: t1 rows 0..63,
                                          // m rows 64..127, u rows 128..191
    float* W1s   = A + KIN * PITCH;       // 192*64
    float* W2s   = W1s + KIN * 64;        // 64*64
    float* Wx1s  = W2s + 64 * 64;         // 64*64
    float* bm1s  = Wx1s + 64 * 64;        // 64
    float* bm2s  = bm1s + 64;
    float* bx1s  = bm2s + 64;
    float* Was   = bx1s + 64;
    float* Wx2s  = Was + 64;
    float* scale_s = Wx2s + 64;           // 128
    float* mask_s  = scale_s + TE;        // 128
    float* dirx  = mask_s + TE;           // 128
    float* diry  = dirx + TE;
    float* dirz  = diry + TE;
    float* bas   = dirz + TE;             // 1 (+3 pad)
    int*   dst_s = (int*)(bas + 4);       // 128

    const int tid = threadIdx.x;

    // ---- stage weights ----
    {
        const float4* s1 = (const float4*)Wm1;  float4* d1 = (float4*)W1s;
        for (int i = tid; i < (KIN * 64) / 4; i += 256) d1[i] = s1[i];
        const float4* s2 = (const float4*)Wm2;  float4* d2 = (float4*)W2s;
        for (int i = tid; i < (64 * 64) / 4; i += 256) d2[i] = s2[i];
        const float4* s3 = (const float4*)Wx1;  float4* d3 = (float4*)Wx1s;
        for (int i = tid; i < (64 * 64) / 4; i += 256) d3[i] = s3[i];
        if (tid < 64) {
            bm1s[tid] = bm1[tid];  bm2s[tid] = bm2[tid];
            bx1s[tid] = bx1[tid];  Was[tid]  = Wa[tid];
            Wx2s[tid] = Wx2[tid];
        }
        if (tid == 0) bas[0] = ba[0];
    }

    // ---- build A tile (2 threads per edge) ----
    const int ebase = blockIdx.x * TE;
    {
        const int e    = tid >> 1;
        const int half = tid & 1;
        const int ge   = ebase + e;
        const int nd   = edst[ge];
        const int ns   = esrc[ge];
        const float dx = x[nd * 3 + 0] - x[ns * 3 + 0];
        const float dy = x[nd * 3 + 1] - x[ns * 3 + 1];
        const float dz = x[nd * 3 + 2] - x[ns * 3 + 2];
        const float dist = sqrtf(dx * dx + dy * dy + dz * dz);
        if (half == 0) {
            const float inv = 1.0f / dist;
            dirx[e] = dx * inv;  diry[e] = dy * inv;  dirz[e] = dz * inv;
            mask_s[e] = (dist <= RCUT) ? 1.0f : 0.0f;
            dst_s[e]  = nd;
        }
        const int f0 = half * 32;
        const float4* hd = (const float4*)(h + (size_t)nd * DIM + f0);
        const float4* hs = (const float4*)(h + (size_t)ns * DIM + f0);
#pragma unroll
        for (int i = 0; i < 8; ++i) {
            const float4 v = hd[i];
            const int f = f0 + i * 4;
            A[(f + 0) * PITCH + e] = v.x;  A[(f + 1) * PITCH + e] = v.y;
            A[(f + 2) * PITCH + e] = v.z;  A[(f + 3) * PITCH + e] = v.w;
        }
#pragma unroll
        for (int i = 0; i < 8; ++i) {
            const float4 v = hs[i];
            const int f = 64 + f0 + i * 4;
            A[(f + 0) * PITCH + e] = v.x;  A[(f + 1) * PITCH + e] = v.y;
            A[(f + 2) * PITCH + e] = v.z;  A[(f + 3) * PITCH + e] = v.w;
        }
#pragma unroll 8
        for (int i = 0; i < 32; ++i) {
            const int g = f0 + i;
            const float t = (dist - __ldg(means + g)) / __ldg(stds + g);
            A[(128 + g) * PITCH + e] = __expf(-0.5f * t * t);
        }
    }
    __syncthreads();

    const int e0 = (tid & 31) * 4;   // 4 edges per thread
    const int j0 = (tid >> 5) * 8;   // 8 output features per thread
    unsigned long long acc2[4][4];
    float acc[4][8];

    // ---- layer 1: [128,192] @ [192,64] ----
    gemm_tile2(A, W1s, KIN, e0, j0, acc2);
    __syncthreads();                       // all reads of A done
    unpack_acc(acc2, acc);
    float* t1 = A;                         // rows 0..63
    store_silu_T(t1, e0, j0, acc, bm1s);
    __syncthreads();

    // ---- layer 2: [128,64] @ [64,64] ----
    gemm_tile2(t1, W2s, 64, e0, j0, acc2);
    unpack_acc(acc2, acc);
    float* mtile = A + 64 * PITCH;         // rows 64..127 (dead A region)
    store_silu_T(mtile, e0, j0, acc, bm2s);
    __syncthreads();

    // ---- attention + mask ----
    if (tid < TE) {
        const int e = tid;
        float s = bas[0];
#pragma unroll 8
        for (int j = 0; j < 64; ++j) s = fmaf(mtile[j * PITCH + e], Was[j], s);
        scale_s[e] = fsigmoid(s) * mask_s[e];
    }
    __syncthreads();

    // ---- scale m in place ----
    for (int i = 0; i < (64 * TE) / 256; ++i) {
        const int lin = tid + i * 256;
        const int e = lin & (TE - 1);
        const int j = lin >> 7;
        mtile[j * PITCH + e] *= scale_s[e];
    }
    __syncthreads();

    // ---- scatter m -> g_msg (vectorized reductions) ----
    for (int i = 0; i < (TE * 16) / 256; ++i) {
        const int q  = tid + i * 256;
        const int e  = q & (TE - 1);
        const int c4 = (q >> 7) * 4;
        const float v0 = mtile[(c4 + 0) * PITCH + e];
        const float v1 = mtile[(c4 + 1) * PITCH + e];
        const float v2 = mtile[(c4 + 2) * PITCH + e];
        const float v3 = mtile[(c4 + 3) * PITCH + e];
        red_add_v4(&g_msg[dst_s[e] * DIM + c4], v0, v1, v2, v3);
    }

    // ---- x path: u = silu(m @ Wx1 + bx1) ----
    gemm_tile2(mtile, Wx1s, 64, e0, j0, acc2);
    unpack_acc(acc2, acc);
    float* utile = A + 128 * PITCH;        // rows 128..191 (dead A region)
    store_silu_T(utile, e0, j0, acc, bx1s);
    __syncthreads();

    // ---- disp magnitude + scatter into x_out ----
    if (tid < TE) {
        const int e = tid;
        float s = 0.0f;
#pragma unroll 8
        for (int j = 0; j < 64; ++j) s = fmaf(utile[j * PITCH + e], Wx2s[j], s);
        const float w = tanhf(s) * mask_s[e];
        float* xo = out + (size_t)NNODES * DIM + dst_s[e] * 3;
        atomicAdd(xo + 0, dirx[e] * w);
        atomicAdd(xo + 1, diry[e] * w);
        atomicAdd(xo + 2, dirz[e] * w);
    }
}

// ---------------------------------------------------------------------------
// Node kernel: h_out = h + silu([h | msg] @ Wh1 + bh1) @ Wh2 + bh2
// ---------------------------------------------------------------------------
__global__ __launch_bounds__(256, 1)
void node_kernel(const float* __restrict__ h,
                 const float* __restrict__ Wh1, const float* __restrict__ bh1,
                 const float* __restrict__ Wh2, const float* __restrict__ bh2,
                 float* __restrict__ out) {
    extern __shared__ float sm[];
    float* A   = sm;                   // [128][PITCH]; t1 aliases rows 0..63 later
    float* W1s = A + 128 * PITCH;      // 128*64
    float* W2s = W1s + 128 * 64;       // 64*64
    float* b1s = W2s + 64 * 64;        // 64
    float* b2s = b1s + 64;             // 64

    const int tid = threadIdx.x;
    {
        const float4* s1 = (const float4*)Wh1;  float4* d1 = (float4*)W1s;
        for (int i = tid; i < (128 * 64) / 4; i += 256) d1[i] = s1[i];
        const float4* s2 = (const float4*)Wh2;  float4* d2 = (float4*)W2s;
        for (int i = tid; i < (64 * 64) / 4; i += 256) d2[i] = s2[i];
        if (tid < 64) { b1s[tid] = bh1[tid]; b2s[tid] = bh2[tid]; }
    }

    const int nbase = blockIdx.x * TE;
    {
        const int nl   = tid >> 1;
        const int half = tid & 1;
        const int n    = nbase + nl;
        const bool ok  = (n < NNODES);
        const float4* src = ok
            ? (half ? (const float4*)(g_msg + (size_t)n * DIM)
                    : (const float4*)(h + (size_t)n * DIM))
            : (const float4*)nullptr;
        const int kbase = half * 64;
#pragma unroll
        for (int i = 0; i < 16; ++i) {
            float4 v = ok ? src[i] : make_float4(0.f, 0.f, 0.f, 0.f);
            const int k = kbase + i * 4;
            A[(k + 0) * PITCH + nl] = v.x;  A[(k + 1) * PITCH + nl] = v.y;
            A[(k + 2) * PITCH + nl] = v.z;  A[(k + 3) * PITCH + nl] = v.w;
        }
    }
    __syncthreads();

    const int e0 = (tid & 31) * 4;
    const int j0 = (tid >> 5) * 8;
    unsigned long long acc2[4][4];
    float acc[4][8];

    gemm_tile2(A, W1s, 128, e0, j0, acc2);
    __syncthreads();
    unpack_acc(acc2, acc);
    float* t1 = A;
    store_silu_T(t1, e0, j0, acc, b1s);
    __syncthreads();

    gemm_tile2(t1, W2s, 64, e0, j0, acc2);
    unpack_acc(acc2, acc);

#pragma unroll
    for (int ee = 0; ee < 4; ++ee) {
        const int n = nbase + e0 + ee;
        if (n < NNODES) {
            const float4 h0 = *(const float4*)(h + (size_t)n * DIM + j0);
            const float4 h1 = *(const float4*)(h + (size_t)n * DIM + j0 + 4);
            float4 o0, o1;
            o0.x = acc[ee][0] + b2s[j0 + 0] + h0.x;
            o0.y = acc[ee][1] + b2s[j0 + 1] + h0.y;
            o0.z = acc[ee][2] + b2s[j0 + 2] + h0.z;
            o0.w = acc[ee][3] + b2s[j0 + 3] + h0.w;
            o1.x = acc[ee][4] + b2s[j0 + 4] + h1.x;
            o1.y = acc[ee][5] + b2s[j0 + 5] + h1.y;
            o1.z = acc[ee][6] + b2s[j0 + 6] + h1.z;
            o1.w = acc[ee][7] + b2s[j0 + 7] + h1.w;
            *(float4*)(out + (size_t)n * DIM + j0)     = o0;
            *(float4*)(out + (size_t)n * DIM + j0 + 4) = o1;
        }
    }
}

// ---------------------------------------------------------------------------
// Launch
// ---------------------------------------------------------------------------
static const int EDGE_SMEM =
    (KIN * PITCH + KIN * 64 + 64 * 64 + 64 * 64 + 64 * 5 + TE * 2 + TE * 3 + 4 + TE)
    * (int)sizeof(float);
static const int NODE_SMEM =
    (128 * PITCH + 128 * 64 + 64 * 64 + 128) * (int)sizeof(float);

extern "C" void kernel_launch(void* const* d_in, const int* in_sizes, int n_in,
                              void* d_out, int out_size) {
    const float* h     = (const float*)d_in[0];
    const float* x     = (const float*)d_in[1];
    const int*   edst  = (const int*)  d_in[2];
    const int*   esrc  = (const int*)  d_in[3];
    const float* means = (const float*)d_in[4];
    const float* stds  = (const float*)d_in[5];
    const float* Wm1   = (const float*)d_in[6];
    const float* bm1   = (const float*)d_in[7];
    const float* Wm2   = (const float*)d_in[8];
    const float* bm2   = (const float*)d_in[9];
    const float* Wa    = (const float*)d_in[10];
    const float* ba    = (const float*)d_in[11];
    const float* Wx1   = (const float*)d_in[12];
    const float* bx1   = (const float*)d_in[13];
    const float* Wx2   = (const float*)d_in[14];
    const float* Wh1   = (const float*)d_in[15];
    const float* bh1   = (const float*)d_in[16];
    const float* Wh2   = (const float*)d_in[17];
    const float* bh2   = (const float*)d_in[18];
    float* out = (float*)d_out;

    cudaFuncSetAttribute(edge_kernel, cudaFuncAttributeMaxDynamicSharedMemorySize, EDGE_SMEM);
    cudaFuncSetAttribute(node_kernel, cudaFuncAttributeMaxDynamicSharedMemorySize, NODE_SMEM);

    init_kernel<<<592, 256>>>(x, out);
    edge_kernel<<<NEDGES / TE, 256, EDGE_SMEM>>>(
        h, x, edst, esrc, means, stds,
        Wm1, bm1, Wm2, bm2, Wa, ba, Wx1, bx1, Wx2, out);
    node_kernel<<<(NNODES + TE - 1) / TE, 256, NODE_SMEM>>>(
        h, Wh1, bh1, Wh2, bh2, out);
}

// round 10
// speedup vs baseline: 1.2303x; 1.0472x over previous
#include <cuda_runtime.h>
#include <cstdint>

// Problem constants
#define NNODES   50000
#define NEDGES   800000
#define DIM      64
#define NG       64
#define KIN      192           // 2*DIM + NG
#define TE       128           // edges (or nodes) per block tile
#define PITCH    132           // TE + 4 padding (float units)
#define RCUT     3.0f
#define NTHR     512

// ---------------------------------------------------------------------------
// Scratch: per-node message accumulator (12.8 MB). __device__ global (no alloc).
// ---------------------------------------------------------------------------
__device__ float g_msg[NNODES * DIM];

__device__ __forceinline__ float fsilu(float v)    { return v / (1.0f + __expf(-v)); }
__device__ __forceinline__ float fsigmoid(float v) { return 1.0f / (1.0f + __expf(-v)); }

__device__ __forceinline__ void red_add_v4(float* addr, float a, float b, float c, float d) {
    asm volatile("red.global.add.v4.f32 [%0], {%1, %2, %3, %4};"
                 :: "l"(addr), "f"(a), "f"(b), "f"(c), "f"(d) : "memory");
}

// ---- packed f32x2 helpers ----
__device__ __forceinline__ unsigned long long pack2(float lo, float hi) {
    unsigned long long r;
    asm("mov.b64 %0, {%1, %2};" : "=l"(r) : "f"(lo), "f"(hi));
    return r;
}
__device__ __forceinline__ void fma2(unsigned long long& d,
                                     unsigned long long a, unsigned long long b) {
    asm("fma.rn.f32x2 %0, %1, %2, %3;" : "=l"(d) : "l"(a), "l"(b), "l"(d));
}
__device__ __forceinline__ void unpack2(unsigned long long v, float& lo, float& hi) {
    asm("mov.b64 {%0, %1}, %2;" : "=f"(lo), "=f"(hi) : "l"(v));
}

// ---------------------------------------------------------------------------
// GEMM fragment: 2 edges x 8 cols per thread, packed f32x2 on the col dim.
// Per k-step: 1 LDS.64 (A pair) + 2 LDS.128 (W, warp-broadcast) + 2 packs
// (4 MOV) + 8 FFMA2 = 15 issues / 16 MACs.
// ---------------------------------------------------------------------------
__device__ __forceinline__ void gemm_tile2(const float* __restrict__ Abuf,
                                           const float* __restrict__ Wbuf,
                                           int K, int e0, int j0,
                                           unsigned long long acc2[2][4]) {
#pragma unroll
    for (int ee = 0; ee < 2; ++ee)
#pragma unroll
        for (int jp = 0; jp < 4; ++jp) acc2[ee][jp] = 0ull;

#pragma unroll 4
    for (int k = 0; k < K; ++k) {
        const float2 a = *(const float2*)(Abuf + k * PITCH + e0);
        const ulonglong2 w0 = *(const ulonglong2*)(Wbuf + (k << 6) + j0);
        const ulonglong2 w1 = *(const ulonglong2*)(Wbuf + (k << 6) + j0 + 4);
        const unsigned long long aa0 = pack2(a.x, a.x);
        const unsigned long long aa1 = pack2(a.y, a.y);
        const unsigned long long wv[4] = {w0.x, w0.y, w1.x, w1.y};
#pragma unroll
        for (int jp = 0; jp < 4; ++jp) {
            fma2(acc2[0][jp], aa0, wv[jp]);
            fma2(acc2[1][jp], aa1, wv[jp]);
        }
    }
}

__device__ __forceinline__ void unpack_acc(const unsigned long long acc2[2][4],
                                           float acc[2][8]) {
#pragma unroll
    for (int ee = 0; ee < 2; ++ee)
#pragma unroll
        for (int jp = 0; jp < 4; ++jp)
            unpack2(acc2[ee][jp], acc[ee][2 * jp], acc[ee][2 * jp + 1]);
}

// silu(acc + bias) transposed into Tbuf[j][e] (pitch PITCH), float2 over e.
__device__ __forceinline__ void store_silu_T(float* __restrict__ Tbuf, int e0, int j0,
                                             const float acc[2][8],
                                             const float* __restrict__ bias) {
#pragma unroll
    for (int jj = 0; jj < 8; ++jj) {
        const float b = bias[j0 + jj];
        float2 v;
        v.x = fsilu(acc[0][jj] + b);
        v.y = fsilu(acc[1][jj] + b);
        *(float2*)(Tbuf + (j0 + jj) * PITCH + e0) = v;
    }
}

// ---------------------------------------------------------------------------
// Init: zero g_msg, copy x into the x-section of out.
// ---------------------------------------------------------------------------
__global__ void init_kernel(const float* __restrict__ x, float* __restrict__ out) {
    const int tid    = blockIdx.x * blockDim.x + threadIdx.x;
    const int stride = gridDim.x * blockDim.x;
    for (int i = tid; i < NNODES * DIM; i += stride) g_msg[i] = 0.0f;
    float* xo = out + (size_t)NNODES * DIM;
    for (int i = tid; i < NNODES * 3; i += stride) xo[i] = x[i];
}

// ---------------------------------------------------------------------------
// Edge kernel: 128 edges / block, 512 threads (16 warps -> 4/SMSP).
// eoffset allows splitting the grid into two launches (profiling alignment).
// ---------------------------------------------------------------------------
__global__ __launch_bounds__(NTHR, 1)
void edge_kernel(const float* __restrict__ h,   const float* __restrict__ x,
                 const int*   __restrict__ edst, const int*  __restrict__ esrc,
                 const float* __restrict__ means, const float* __restrict__ stds,
                 const float* __restrict__ Wm1, const float* __restrict__ bm1,
                 const float* __restrict__ Wm2, const float* __restrict__ bm2,
                 const float* __restrict__ Wa,  const float* __restrict__ ba,
                 const float* __restrict__ Wx1, const float* __restrict__ bx1,
                 const float* __restrict__ Wx2,
                 float* __restrict__ out, int eoffset) {
    extern __shared__ float sm[];
    float* A     = sm;                    // [KIN][PITCH]; aliased: t1 rows 0..63,
                                          // m rows 64..127, u rows 128..191
    float* W1s   = A + KIN * PITCH;       // 192*64
    float* W2s   = W1s + KIN * 64;        // 64*64
    float* Wx1s  = W2s + 64 * 64;         // 64*64
    float* bm1s  = Wx1s + 64 * 64;        // 64
    float* bm2s  = bm1s + 64;
    float* bx1s  = bm2s + 64;
    float* Was   = bx1s + 64;
    float* Wx2s  = Was + 64;
    float* scale_s = Wx2s + 64;           // 128
    float* mask_s  = scale_s + TE;        // 128
    float* dirx  = mask_s + TE;           // 128
    float* diry  = dirx + TE;
    float* dirz  = diry + TE;
    float* bas   = dirz + TE;             // 1 (+3 pad)
    int*   dst_s = (int*)(bas + 4);       // 128

    const int tid = threadIdx.x;

    // ---- stage weights ----
    {
        const float4* s1 = (const float4*)Wm1;  float4* d1 = (float4*)W1s;
        for (int i = tid; i < (KIN * 64) / 4; i += NTHR) d1[i] = s1[i];
        const float4* s2 = (const float4*)Wm2;  float4* d2 = (float4*)W2s;
        for (int i = tid; i < (64 * 64) / 4; i += NTHR) d2[i] = s2[i];
        const float4* s3 = (const float4*)Wx1;  float4* d3 = (float4*)Wx1s;
        for (int i = tid; i < (64 * 64) / 4; i += NTHR) d3[i] = s3[i];
        if (tid < 64) {
            bm1s[tid] = bm1[tid];  bm2s[tid] = bm2[tid];
            bx1s[tid] = bx1[tid];  Was[tid]  = Wa[tid];
            Wx2s[tid] = Wx2[tid];
        }
        if (tid == 0) bas[0] = ba[0];
    }

    // ---- build A tile (4 threads per edge, 16 features each) ----
    const int ebase = (blockIdx.x + eoffset) * TE;
    {
        const int e = tid >> 2;
        const int q = tid & 3;
        const int ge = ebase + e;
        const int nd = edst[ge];
        const int ns = esrc[ge];
        const float dx = x[nd * 3 + 0] - x[ns * 3 + 0];
        const float dy = x[nd * 3 + 1] - x[ns * 3 + 1];
        const float dz = x[nd * 3 + 2] - x[ns * 3 + 2];
        const float dist = sqrtf(dx * dx + dy * dy + dz * dz);
        if (q == 0) {
            const float inv = 1.0f / dist;
            dirx[e] = dx * inv;  diry[e] = dy * inv;  dirz[e] = dz * inv;
            mask_s[e] = (dist <= RCUT) ? 1.0f : 0.0f;
            dst_s[e]  = nd;
        }
        const int f0 = q * 16;
        const float4* hd = (const float4*)(h + (size_t)nd * DIM + f0);
        const float4* hs = (const float4*)(h + (size_t)ns * DIM + f0);
#pragma unroll
        for (int i = 0; i < 4; ++i) {
            const float4 v = hd[i];
            const int f = f0 + i * 4;
            A[(f + 0) * PITCH + e] = v.x;  A[(f + 1) * PITCH + e] = v.y;
            A[(f + 2) * PITCH + e] = v.z;  A[(f + 3) * PITCH + e] = v.w;
        }
#pragma unroll
        for (int i = 0; i < 4; ++i) {
            const float4 v = hs[i];
            const int f = 64 + f0 + i * 4;
            A[(f + 0) * PITCH + e] = v.x;  A[(f + 1) * PITCH + e] = v.y;
            A[(f + 2) * PITCH + e] = v.z;  A[(f + 3) * PITCH + e] = v.w;
        }
#pragma unroll 8
        for (int i = 0; i < 16; ++i) {
            const int g = f0 + i;
            const float t = (dist - __ldg(means + g)) / __ldg(stds + g);
            A[(128 + g) * PITCH + e] = __expf(-0.5f * t * t);
        }
    }
    __syncthreads();

    const int e0 = (tid & 63) * 2;   // 2 edges per thread
    const int j0 = (tid >> 6) * 8;   // 8 output features per thread
    unsigned long long acc2[2][4];
    float acc[2][8];

    // ---- layer 1: [128,192] @ [192,64] ----
    gemm_tile2(A, W1s, KIN, e0, j0, acc2);
    __syncthreads();                       // all reads of A done
    unpack_acc(acc2, acc);
    float* t1 = A;                         // rows 0..63
    store_silu_T(t1, e0, j0, acc, bm1s);
    __syncthreads();

    // ---- layer 2: [128,64] @ [64,64] ----
    gemm_tile2(t1, W2s, 64, e0, j0, acc2);
    unpack_acc(acc2, acc);
    float* mtile = A + 64 * PITCH;         // rows 64..127 (dead A region)
    store_silu_T(mtile, e0, j0, acc, bm2s);
    __syncthreads();

    // ---- attention + mask ----
    if (tid < TE) {
        const int e = tid;
        float s = bas[0];
#pragma unroll 8
        for (int j = 0; j < 64; ++j) s = fmaf(mtile[j * PITCH + e], Was[j], s);
        scale_s[e] = fsigmoid(s) * mask_s[e];
    }
    __syncthreads();

    // ---- scale m in place ----
    for (int i = 0; i < (64 * TE) / NTHR; ++i) {
        const int lin = tid + i * NTHR;
        const int e = lin & (TE - 1);
        const int j = lin >> 7;
        mtile[j * PITCH + e] *= scale_s[e];
    }
    __syncthreads();

    // ---- scatter m -> g_msg (vectorized reductions) ----
    for (int i = 0; i < (TE * 16) / NTHR; ++i) {
        const int q  = tid + i * NTHR;
        const int e  = q & (TE - 1);
        const int c4 = (q >> 7) * 4;
        const float v0 = mtile[(c4 + 0) * PITCH + e];
        const float v1 = mtile[(c4 + 1) * PITCH + e];
        const float v2 = mtile[(c4 + 2) * PITCH + e];
        const float v3 = mtile[(c4 + 3) * PITCH + e];
        red_add_v4(&g_msg[dst_s[e] * DIM + c4], v0, v1, v2, v3);
    }

    // ---- x path: u = silu(m @ Wx1 + bx1) ----
    gemm_tile2(mtile, Wx1s, 64, e0, j0, acc2);
    unpack_acc(acc2, acc);
    float* utile = A + 128 * PITCH;        // rows 128..191 (dead A region)
    store_silu_T(utile, e0, j0, acc, bx1s);
    __syncthreads();

    // ---- disp magnitude + scatter into x_out ----
    if (tid < TE) {
        const int e = tid;
        float s = 0.0f;
#pragma unroll 8
        for (int j = 0; j < 64; ++j) s = fmaf(utile[j * PITCH + e], Wx2s[j], s);
        const float w = tanhf(s) * mask_s[e];
        float* xo = out + (size_t)NNODES * DIM + dst_s[e] * 3;
        atomicAdd(xo + 0, dirx[e] * w);
        atomicAdd(xo + 1, diry[e] * w);
        atomicAdd(xo + 2, dirz[e] * w);
    }
}

// ---------------------------------------------------------------------------
// Node kernel: h_out = h + silu([h | msg] @ Wh1 + bh1) @ Wh2 + bh2
// 128 nodes / block, 512 threads.
// ---------------------------------------------------------------------------
__global__ __launch_bounds__(NTHR, 1)
void node_kernel(const float* __restrict__ h,
                 const float* __restrict__ Wh1, const float* __restrict__ bh1,
                 const float* __restrict__ Wh2, const float* __restrict__ bh2,
                 float* __restrict__ out) {
    extern __shared__ float sm[];
    float* A   = sm;                   // [128][PITCH]; t1 aliases rows 0..63 later
    float* W1s = A + 128 * PITCH;      // 128*64
    float* W2s = W1s + 128 * 64;       // 64*64
    float* b1s = W2s + 64 * 64;        // 64
    float* b2s = b1s + 64;             // 64

    const int tid = threadIdx.x;
    {
        const float4* s1 = (const float4*)Wh1;  float4* d1 = (float4*)W1s;
        for (int i = tid; i < (128 * 64) / 4; i += NTHR) d1[i] = s1[i];
        const float4* s2 = (const float4*)Wh2;  float4* d2 = (float4*)W2s;
        for (int i = tid; i < (64 * 64) / 4; i += NTHR) d2[i] = s2[i];
        if (tid < 64) { b1s[tid] = bh1[tid]; b2s[tid] = bh2[tid]; }
    }

    const int nbase = blockIdx.x * TE;
    {
        const int nl = tid >> 2;           // node within tile
        const int q  = tid & 3;            // 32-feature quarter
        const int n  = nbase + nl;
        const bool ok = (n < NNODES);
        const float* srcp = (q < 2) ? (h + (size_t)n * DIM + q * 32)
                                    : (g_msg + (size_t)n * DIM + (q - 2) * 32);
        const int kbase = q * 32;
#pragma unroll
        for (int i = 0; i < 8; ++i) {
            float4 v = ok ? ((const float4*)srcp)[i] : make_float4(0.f, 0.f, 0.f, 0.f);
            const int k = kbase + i * 4;
            A[(k + 0) * PITCH + nl] = v.x;  A[(k + 1) * PITCH + nl] = v.y;
            A[(k + 2) * PITCH + nl] = v.z;  A[(k + 3) * PITCH + nl] = v.w;
        }
    }
    __syncthreads();

    const int e0 = (tid & 63) * 2;
    const int j0 = (tid >> 6) * 8;
    unsigned long long acc2[2][4];
    float acc[2][8];

    gemm_tile2(A, W1s, 128, e0, j0, acc2);
    __syncthreads();
    unpack_acc(acc2, acc);
    float* t1 = A;
    store_silu_T(t1, e0, j0, acc, b1s);
    __syncthreads();

    gemm_tile2(t1, W2s, 64, e0, j0, acc2);
    unpack_acc(acc2, acc);

#pragma unroll
    for (int ee = 0; ee < 2; ++ee) {
        const int n = nbase + e0 + ee;
        if (n < NNODES) {
            const float4 h0 = *(const float4*)(h + (size_t)n * DIM + j0);
            const float4 h1 = *(const float4*)(h + (size_t)n * DIM + j0 + 4);
            float4 o0, o1;
            o0.x = acc[ee][0] + b2s[j0 + 0] + h0.x;
            o0.y = acc[ee][1] + b2s[j0 + 1] + h0.y;
            o0.z = acc[ee][2] + b2s[j0 + 2] + h0.z;
            o0.w = acc[ee][3] + b2s[j0 + 3] + h0.w;
            o1.x = acc[ee][4] + b2s[j0 + 4] + h1.x;
            o1.y = acc[ee][5] + b2s[j0 + 5] + h1.y;
            o1.z = acc[ee][6] + b2s[j0 + 6] + h1.z;
            o1.w = acc[ee][7] + b2s[j0 + 7] + h1.w;
            *(float4*)(out + (size_t)n * DIM + j0)     = o0;
            *(float4*)(out + (size_t)n * DIM + j0 + 4) = o1;
        }
    }
}

// ---------------------------------------------------------------------------
// Launch
// ---------------------------------------------------------------------------
static const int EDGE_SMEM =
    (KIN * PITCH + KIN * 64 + 64 * 64 + 64 * 64 + 64 * 5 + TE * 2 + TE * 3 + 4 + TE)
    * (int)sizeof(float);
static const int NODE_SMEM =
    (128 * PITCH + 128 * 64 + 64 * 64 + 128) * (int)sizeof(float);

extern "C" void kernel_launch(void* const* d_in, const int* in_sizes, int n_in,
                              void* d_out, int out_size) {
    const float* h     = (const float*)d_in[0];
    const float* x     = (const float*)d_in[1];
    const int*   edst  = (const int*)  d_in[2];
    const int*   esrc  = (const int*)  d_in[3];
    const float* means = (const float*)d_in[4];
    const float* stds  = (const float*)d_in[5];
    const float* Wm1   = (const float*)d_in[6];
    const float* bm1   = (const float*)d_in[7];
    const float* Wm2   = (const float*)d_in[8];
    const float* bm2   = (const float*)d_in[9];
    const float* Wa    = (const float*)d_in[10];
    const float* ba    = (const float*)d_in[11];
    const float* Wx1   = (const float*)d_in[12];
    const float* bx1   = (const float*)d_in[13];
    const float* Wx2   = (const float*)d_in[14];
    const float* Wh1   = (const float*)d_in[15];
    const float* bh1   = (const float*)d_in[16];
    const float* Wh2   = (const float*)d_in[17];
    const float* bh2   = (const float*)d_in[18];
    float* out = (float*)d_out;

    cudaFuncSetAttribute(edge_kernel, cudaFuncAttributeMaxDynamicSharedMemorySize, EDGE_SMEM);
    cudaFuncSetAttribute(node_kernel, cudaFuncAttributeMaxDynamicSharedMemorySize, NODE_SMEM);

    const int EBLOCKS = NEDGES / TE;       // 6250
    const int HALF    = EBLOCKS / 2;       // 3125

    init_kernel<<<592, 256>>>(x, out);
    edge_kernel<<<HALF, NTHR, EDGE_SMEM>>>(
        h, x, edst, esrc, means, stds,
        Wm1, bm1, Wm2, bm2, Wa, ba, Wx1, bx1, Wx2, out, 0);
    edge_kernel<<<EBLOCKS - HALF, NTHR, EDGE_SMEM>>>(
        h, x, edst, esrc, means, stds,
        Wm1, bm1, Wm2, bm2, Wa, ba, Wx1, bx1, Wx2, out, HALF);
    node_kernel<<<(NNODES + TE - 1) / TE, NTHR, NODE_SMEM>>>(
        h, Wh1, bh1, Wh2, bh2, out);
}